// round 1
// baseline (speedup 1.0000x reference)
#include <cuda_runtime.h>
#include <cuda_bf16.h>

// SGC K=2:  out = Prop(Prop(x @ W)) + b      (projection commuted to the front)
// Prop(h)[i] = norm[i] * sum_{e: dst[e]==i} h[src[e]] * norm[src[e]]
// norm[i] = rsqrt(max(in_deg[i], 1))

#define NN 100000
#define EE 3200000
#define IN_F 256
#define OUT_F 64

// ---------------- scratch (static device globals; no allocation) -------------
__device__ float g_y0[NN * OUT_F];    // x @ W
__device__ float g_accA[NN * OUT_F];  // round-1 scatter accumulator
__device__ float g_accB[NN * OUT_F];  // round-2 scatter accumulator
__device__ float g_norm[NN];
__device__ int   g_deg[NN];

// ---------------- degree + norm ---------------------------------------------
__global__ void deg_kernel(const int* __restrict__ dst, int E) {
    int e = blockIdx.x * blockDim.x + threadIdx.x;
    if (e < E) atomicAdd(&g_deg[dst[e]], 1);
}

__global__ void norm_kernel(int N) {
    int i = blockIdx.x * blockDim.x + threadIdx.x;
    if (i < N) {
        float d = (float)g_deg[i];
        g_norm[i] = rsqrtf(fmaxf(d, 1.0f));
    }
}

// ---------------- y0 = x @ W  (100k x 256 @ 256 x 64) ------------------------
// 64 rows x 64 cols per block, 256 threads, 4x4 register micro-tile,
// K chunked by 64.  HBM floor ~13us for the 102MB x read.
__global__ void __launch_bounds__(256) gemm_kernel(const float* __restrict__ x,
                                                   const float* __restrict__ W,
                                                   float* __restrict__ y0, int N) {
    __shared__ float Xs[64][65];   // +1 pad: conflict-free column reads
    __shared__ float Ws[64][64];   // [k][col]; rows are 256B -> float4 aligned

    const int t = threadIdx.x;
    const int rowbase = blockIdx.x * 64;
    const int tc = t & 15;         // 0..15 -> col group
    const int tr = t >> 4;         // 0..15 -> row group
    const int col0 = tc * 4;
    const int row0 = tr * 4;

    float acc[4][4] = {};

    for (int kc = 0; kc < IN_F; kc += 64) {
        #pragma unroll
        for (int i = 0; i < 16; i++) {
            int lin = t + i * 256;
            int r = lin >> 6;      // 0..63
            int c = lin & 63;      // 0..63
            int gr = rowbase + r;
            Xs[r][c] = (gr < N) ? x[(long long)gr * IN_F + kc + c] : 0.0f;
            Ws[r][c] = W[(kc + r) * OUT_F + c];
        }
        __syncthreads();

        #pragma unroll
        for (int k = 0; k < 64; k++) {
            float4 wv = *(const float4*)&Ws[k][col0];
            float xa0 = Xs[row0 + 0][k];
            float xa1 = Xs[row0 + 1][k];
            float xa2 = Xs[row0 + 2][k];
            float xa3 = Xs[row0 + 3][k];
            acc[0][0] += xa0 * wv.x; acc[0][1] += xa0 * wv.y;
            acc[0][2] += xa0 * wv.z; acc[0][3] += xa0 * wv.w;
            acc[1][0] += xa1 * wv.x; acc[1][1] += xa1 * wv.y;
            acc[1][2] += xa1 * wv.z; acc[1][3] += xa1 * wv.w;
            acc[2][0] += xa2 * wv.x; acc[2][1] += xa2 * wv.y;
            acc[2][2] += xa2 * wv.z; acc[2][3] += xa2 * wv.w;
            acc[3][0] += xa3 * wv.x; acc[3][1] += xa3 * wv.y;
            acc[3][2] += xa3 * wv.z; acc[3][3] += xa3 * wv.w;
        }
        __syncthreads();
    }

    #pragma unroll
    for (int r = 0; r < 4; r++) {
        int gr = rowbase + row0 + r;
        if (gr < N) {
            float4 v = make_float4(acc[r][0], acc[r][1], acc[r][2], acc[r][3]);
            *(float4*)&y0[(long long)gr * OUT_F + col0] = v;
        }
    }
}

// ---------------- edge scatter: acc[dst] += y[src] * norm[src]^{1 or 2} ------
// 16 threads per edge, one float4 + one red.global.add.v4 each.
template <bool SQ>
__global__ void __launch_bounds__(256) edge_kernel(const float* __restrict__ y,
                                                   float* __restrict__ acc,
                                                   const int* __restrict__ src,
                                                   const int* __restrict__ dst,
                                                   int E) {
    int gid = blockIdx.x * blockDim.x + threadIdx.x;
    int e = gid >> 4;
    if (e >= E) return;
    int lane = gid & 15;

    int s = __ldg(&src[e]);
    int d = __ldg(&dst[e]);
    float ns = __ldg(&g_norm[s]);
    if (SQ) ns *= ns;

    float4 v = __ldg(((const float4*)y) + (s * 16 + lane));
    float4 o = make_float4(v.x * ns, v.y * ns, v.z * ns, v.w * ns);

    float* p = acc + ((long long)d * OUT_F + lane * 4);
    asm volatile("red.global.add.v4.f32 [%0], {%1,%2,%3,%4};"
                 :: "l"(p), "f"(o.x), "f"(o.y), "f"(o.z), "f"(o.w)
                 : "memory");
}

// ---------------- epilogue: out = accB * norm + b ----------------------------
__global__ void final_kernel(const float* __restrict__ acc,
                             const float* __restrict__ b,
                             float* __restrict__ out, int N) {
    int gid = blockIdx.x * blockDim.x + threadIdx.x;
    if (gid >= N * 16) return;
    int i = gid >> 4;
    int lane = gid & 15;
    float nm = __ldg(&g_norm[i]);
    float4 v = __ldg(((const float4*)acc) + gid);
    float4 bb = __ldg(((const float4*)b) + lane);
    float4 o = make_float4(v.x * nm + bb.x, v.y * nm + bb.y,
                           v.z * nm + bb.z, v.w * nm + bb.w);
    ((float4*)out)[gid] = o;
}

// ---------------- launch -----------------------------------------------------
extern "C" void kernel_launch(void* const* d_in, const int* in_sizes, int n_in,
                              void* d_out, int out_size) {
    const float* x   = (const float*)d_in[0];
    const int*   src = (const int*)d_in[1];
    const int*   dst = (const int*)d_in[2];
    const float* W   = (const float*)d_in[3];
    const float* b   = (const float*)d_in[4];
    float*       out = (float*)d_out;

    const int N = in_sizes[0] / IN_F;   // 100000
    const int E = in_sizes[1];          // 3200000

    void *p_deg, *p_accA, *p_accB, *p_y0;
    cudaGetSymbolAddress(&p_deg,  g_deg);
    cudaGetSymbolAddress(&p_accA, g_accA);
    cudaGetSymbolAddress(&p_accB, g_accB);
    cudaGetSymbolAddress(&p_y0,   g_y0);

    cudaMemsetAsync(p_deg,  0, (size_t)N * sizeof(int));
    cudaMemsetAsync(p_accA, 0, (size_t)N * OUT_F * sizeof(float));
    cudaMemsetAsync(p_accB, 0, (size_t)N * OUT_F * sizeof(float));

    deg_kernel<<<(E + 255) / 256, 256>>>(dst, E);
    norm_kernel<<<(N + 255) / 256, 256>>>(N);

    gemm_kernel<<<(N + 63) / 64, 256>>>(x, W, (float*)p_y0, N);

    const int ethreads = E * 16;
    const int eblocks = (ethreads + 255) / 256;

    // round 1: accA += y0[src] * norm[src]
    edge_kernel<false><<<eblocks, 256>>>((const float*)p_y0, (float*)p_accA,
                                         src, dst, E);
    // round 2: accB += accA[src] * norm[src]^2   (fused post*pre scale)
    edge_kernel<true><<<eblocks, 256>>>((const float*)p_accA, (float*)p_accB,
                                        src, dst, E);

    // out = accB * norm + b
    final_kernel<<<(N * 16 + 255) / 256, 256>>>((const float*)p_accB, b, out, N);
}

// round 4
// speedup vs baseline: 1.7724x; 1.7724x over previous
#include <cuda_runtime.h>
#include <cuda_bf16.h>

// SGC K=2:  out = Prop(Prop(x @ W)) + b   (projection commuted to the front)
// Pull-based aggregation over a per-call CSR (edges grouped by dst).
//   y0n[i] = (x@W)[i] * norm[i]
//   z1[i]  = (sum_{s in N(i)} y0n[s]) * norm[i]^2
//   out[i] = (sum_{s in N(i)} z1[s]) * norm[i] + b

#define NN 100000
#define EE 3200000
#define IN_F 256
#define OUT_F 64
#define SCAN_B 1024
#define SCAN_NB ((NN + SCAN_B - 1) / SCAN_B)   // 98

// ---------------- scratch (static device globals; no allocation) -------------
__device__ float g_y0n[NN * OUT_F];   // (x@W)*norm
__device__ float g_z1[NN * OUT_F];    // round-1 result, pre-scaled by norm^2
__device__ float g_norm[NN];
__device__ int   g_deg[NN];
__device__ int   g_off[NN];           // CSR row offsets (exclusive scan of deg)
__device__ int   g_cur[NN];           // scatter cursors
__device__ int   g_csr[EE];           // src ids grouped by dst
__device__ int   g_part[SCAN_NB];     // scan partials

// ---------------- degree histogram -------------------------------------------
__global__ void deg_kernel(const int* __restrict__ dst, int E) {
    int e = blockIdx.x * blockDim.x + threadIdx.x;
    if (e < E) atomicAdd(&g_deg[dst[e]], 1);
}

// ---------------- scan stage 1: per-block sums -------------------------------
__global__ void __launch_bounds__(SCAN_B) scan1_kernel(int N) {
    __shared__ int sh[SCAN_B];
    int t = threadIdx.x;
    int i = blockIdx.x * SCAN_B + t;
    int v = (i < N) ? g_deg[i] : 0;
    sh[t] = v;
    __syncthreads();
    for (int o = SCAN_B / 2; o > 0; o >>= 1) {
        if (t < o) sh[t] += sh[t + o];
        __syncthreads();
    }
    if (t == 0) g_part[blockIdx.x] = sh[0];
}

// ---------------- scan stage 2: serial exclusive scan of partials ------------
__global__ void scan2_kernel() {
    if (threadIdx.x == 0) {
        int run = 0;
        for (int i = 0; i < SCAN_NB; i++) {
            int v = g_part[i];
            g_part[i] = run;
            run += v;
        }
    }
}

// ---------------- scan stage 3: block-local exclusive scan + norm ------------
__global__ void __launch_bounds__(SCAN_B) scan3_kernel(int N) {
    __shared__ int sh[SCAN_B];
    int t = threadIdx.x;
    int i = blockIdx.x * SCAN_B + t;
    int v = (i < N) ? g_deg[i] : 0;
    sh[t] = v;
    __syncthreads();
    // Hillis-Steele inclusive scan
    for (int o = 1; o < SCAN_B; o <<= 1) {
        int a = (t >= o) ? sh[t - o] : 0;
        __syncthreads();
        sh[t] += a;
        __syncthreads();
    }
    if (i < N) {
        int excl = sh[t] - v + g_part[blockIdx.x];
        g_off[i] = excl;
        g_cur[i] = excl;
        g_norm[i] = rsqrtf(fmaxf((float)v, 1.0f));
    }
}

// ---------------- CSR fill: group src by dst ---------------------------------
__global__ void scatter_kernel(const int* __restrict__ src,
                               const int* __restrict__ dst, int E) {
    int e = blockIdx.x * blockDim.x + threadIdx.x;
    if (e < E) {
        int pos = atomicAdd(&g_cur[dst[e]], 1);
        g_csr[pos] = src[e];
    }
}

// ---------------- y0n = (x @ W) * norm  (100k x 256 @ 256 x 64) --------------
__global__ void __launch_bounds__(256) gemm_kernel(const float* __restrict__ x,
                                                   const float* __restrict__ W,
                                                   float* __restrict__ y0n, int N) {
    __shared__ float Xs[64][65];
    __shared__ float Ws[64][64];

    const int t = threadIdx.x;
    const int rowbase = blockIdx.x * 64;
    const int tc = t & 15;
    const int tr = t >> 4;
    const int col0 = tc * 4;
    const int row0 = tr * 4;

    float acc[4][4] = {};

    for (int kc = 0; kc < IN_F; kc += 64) {
        #pragma unroll
        for (int i = 0; i < 16; i++) {
            int lin = t + i * 256;
            int r = lin >> 6;
            int c = lin & 63;
            int gr = rowbase + r;
            Xs[r][c] = (gr < N) ? x[(long long)gr * IN_F + kc + c] : 0.0f;
            Ws[r][c] = W[(kc + r) * OUT_F + c];
        }
        __syncthreads();

        #pragma unroll
        for (int k = 0; k < 64; k++) {
            float4 wv = *(const float4*)&Ws[k][col0];
            float xa0 = Xs[row0 + 0][k];
            float xa1 = Xs[row0 + 1][k];
            float xa2 = Xs[row0 + 2][k];
            float xa3 = Xs[row0 + 3][k];
            acc[0][0] += xa0 * wv.x; acc[0][1] += xa0 * wv.y;
            acc[0][2] += xa0 * wv.z; acc[0][3] += xa0 * wv.w;
            acc[1][0] += xa1 * wv.x; acc[1][1] += xa1 * wv.y;
            acc[1][2] += xa1 * wv.z; acc[1][3] += xa1 * wv.w;
            acc[2][0] += xa2 * wv.x; acc[2][1] += xa2 * wv.y;
            acc[2][2] += xa2 * wv.z; acc[2][3] += xa2 * wv.w;
            acc[3][0] += xa3 * wv.x; acc[3][1] += xa3 * wv.y;
            acc[3][2] += xa3 * wv.z; acc[3][3] += xa3 * wv.w;
        }
        __syncthreads();
    }

    #pragma unroll
    for (int r = 0; r < 4; r++) {
        int gr = rowbase + row0 + r;
        if (gr < N) {
            float nm = g_norm[gr];
            float4 v = make_float4(acc[r][0] * nm, acc[r][1] * nm,
                                   acc[r][2] * nm, acc[r][3] * nm);
            *(float4*)&y0n[(long long)gr * OUT_F + col0] = v;
        }
    }
}

// ---------------- pull round 1: z1[i] = (sum y0n[s]) * norm[i]^2 -------------
// one warp per node, lane owns 2 floats of the 64-wide feature
__global__ void __launch_bounds__(256) pull1_kernel(const float* __restrict__ y,
                                                    float* __restrict__ z, int N) {
    int warp = (blockIdx.x * blockDim.x + threadIdx.x) >> 5;
    if (warp >= N) return;
    int lane = threadIdx.x & 31;
    int base = g_off[warp];
    int deg = g_deg[warp];
    const float2* yp = (const float2*)y;
    const int* cp = g_csr + base;

    float ax = 0.0f, ay = 0.0f;
    int j = 0;
    for (; j + 4 <= deg; j += 4) {
        int s0 = __ldg(cp + j + 0);
        int s1 = __ldg(cp + j + 1);
        int s2 = __ldg(cp + j + 2);
        int s3 = __ldg(cp + j + 3);
        float2 v0 = __ldg(yp + s0 * 32 + lane);
        float2 v1 = __ldg(yp + s1 * 32 + lane);
        float2 v2 = __ldg(yp + s2 * 32 + lane);
        float2 v3 = __ldg(yp + s3 * 32 + lane);
        ax += v0.x + v1.x + v2.x + v3.x;
        ay += v0.y + v1.y + v2.y + v3.y;
    }
    for (; j < deg; j++) {
        int s = __ldg(cp + j);
        float2 v = __ldg(yp + s * 32 + lane);
        ax += v.x;
        ay += v.y;
    }
    float nm = g_norm[warp];
    nm *= nm;
    ((float2*)z)[warp * 32 + lane] = make_float2(ax * nm, ay * nm);
}

// ---------------- pull round 2: out[i] = (sum z1[s]) * norm[i] + b -----------
__global__ void __launch_bounds__(256) pull2_kernel(const float* __restrict__ z,
                                                    const float* __restrict__ b,
                                                    float* __restrict__ out, int N) {
    int warp = (blockIdx.x * blockDim.x + threadIdx.x) >> 5;
    if (warp >= N) return;
    int lane = threadIdx.x & 31;
    int base = g_off[warp];
    int deg = g_deg[warp];
    const float2* zp = (const float2*)z;
    const int* cp = g_csr + base;

    float ax = 0.0f, ay = 0.0f;
    int j = 0;
    for (; j + 4 <= deg; j += 4) {
        int s0 = __ldg(cp + j + 0);
        int s1 = __ldg(cp + j + 1);
        int s2 = __ldg(cp + j + 2);
        int s3 = __ldg(cp + j + 3);
        float2 v0 = __ldg(zp + s0 * 32 + lane);
        float2 v1 = __ldg(zp + s1 * 32 + lane);
        float2 v2 = __ldg(zp + s2 * 32 + lane);
        float2 v3 = __ldg(zp + s3 * 32 + lane);
        ax += v0.x + v1.x + v2.x + v3.x;
        ay += v0.y + v1.y + v2.y + v3.y;
    }
    for (; j < deg; j++) {
        int s = __ldg(cp + j);
        float2 v = __ldg(zp + s * 32 + lane);
        ax += v.x;
        ay += v.y;
    }
    float nm = g_norm[warp];
    float2 bb = __ldg((const float2*)b + lane);
    ((float2*)out)[warp * 32 + lane] =
        make_float2(ax * nm + bb.x, ay * nm + bb.y);
}

// ---------------- launch -----------------------------------------------------
extern "C" void kernel_launch(void* const* d_in, const int* in_sizes, int n_in,
                              void* d_out, int out_size) {
    const float* x   = (const float*)d_in[0];
    const int*   src = (const int*)d_in[1];
    const int*   dst = (const int*)d_in[2];
    const float* W   = (const float*)d_in[3];
    const float* b   = (const float*)d_in[4];
    float*       out = (float*)d_out;

    const int N = in_sizes[0] / IN_F;   // 100000
    const int E = in_sizes[1];          // 3200000

    void *p_deg, *p_y0n, *p_z1;
    cudaGetSymbolAddress(&p_deg, g_deg);
    cudaGetSymbolAddress(&p_y0n, g_y0n);
    cudaGetSymbolAddress(&p_z1,  g_z1);

    cudaMemsetAsync(p_deg, 0, (size_t)N * sizeof(int));

    // CSR build
    deg_kernel<<<(E + 255) / 256, 256>>>(dst, E);
    scan1_kernel<<<SCAN_NB, SCAN_B>>>(N);
    scan2_kernel<<<1, 32>>>();
    scan3_kernel<<<SCAN_NB, SCAN_B>>>(N);
    scatter_kernel<<<(E + 255) / 256, 256>>>(src, dst, E);

    // projection (scaled by norm at write)
    gemm_kernel<<<(N + 63) / 64, 256>>>(x, W, (float*)p_y0n, N);

    // two pull rounds (warp per node)
    const int pb = 256;
    const int pgrid = (N * 32 + pb - 1) / pb;
    pull1_kernel<<<pgrid, pb>>>((const float*)p_y0n, (float*)p_z1, N);
    pull2_kernel<<<pgrid, pb>>>((const float*)p_z1, b, out, N);
}

// round 5
// speedup vs baseline: 1.7968x; 1.0138x over previous
#include <cuda_runtime.h>
#include <cuda_fp16.h>

// SGC K=2:  out = Prop(Prop(x @ W)) + b   (projection commuted to the front)
// Pull-based aggregation over a per-call CSR (edges grouped by dst).
// Propagated features stored in fp16 (halves L2 gather bytes); fp32 accumulate.
//   y0h[i] = fp16( (x@W)[i] * norm[i] )
//   z1h[i] = fp16( (sum_{s in N(i)} y0h[s]) * norm[i]^2 )
//   out[i] =      (sum_{s in N(i)} z1h[s]) * norm[i] + b

#define NN 100000
#define EE 3200000
#define IN_F 256
#define OUT_F 64
#define SCAN_B 1024
#define SCAN_NB ((NN + SCAN_B - 1) / SCAN_B)   // 98

// ---------------- scratch (static device globals; no allocation) -------------
__device__ __half g_y0h[NN * OUT_F];  // (x@W)*norm, fp16
__device__ __half g_z1h[NN * OUT_F];  // round-1 result * norm^2, fp16
__device__ float  g_norm[NN];
__device__ int    g_deg[NN];
__device__ int    g_off[NN];          // CSR row offsets
__device__ int    g_cur[NN];          // scatter cursors
__device__ int    g_csr[EE];          // src ids grouped by dst
__device__ int    g_part[SCAN_NB];    // scan partials

// ---------------- degree histogram -------------------------------------------
__global__ void deg_kernel(const int* __restrict__ dst, int E) {
    int e = blockIdx.x * blockDim.x + threadIdx.x;
    if (e < E) atomicAdd(&g_deg[dst[e]], 1);
}

// ---------------- scan stage 1: per-block sums -------------------------------
__global__ void __launch_bounds__(SCAN_B) scan1_kernel(int N) {
    __shared__ int sh[SCAN_B];
    int t = threadIdx.x;
    int i = blockIdx.x * SCAN_B + t;
    int v = (i < N) ? g_deg[i] : 0;
    sh[t] = v;
    __syncthreads();
    for (int o = SCAN_B / 2; o > 0; o >>= 1) {
        if (t < o) sh[t] += sh[t + o];
        __syncthreads();
    }
    if (t == 0) g_part[blockIdx.x] = sh[0];
}

// ---------------- scan stage 2: serial exclusive scan of partials ------------
__global__ void scan2_kernel() {
    if (threadIdx.x == 0) {
        int run = 0;
        for (int i = 0; i < SCAN_NB; i++) {
            int v = g_part[i];
            g_part[i] = run;
            run += v;
        }
    }
}

// ---------------- scan stage 3: block-local exclusive scan + norm ------------
__global__ void __launch_bounds__(SCAN_B) scan3_kernel(int N) {
    __shared__ int sh[SCAN_B];
    int t = threadIdx.x;
    int i = blockIdx.x * SCAN_B + t;
    int v = (i < N) ? g_deg[i] : 0;
    sh[t] = v;
    __syncthreads();
    for (int o = 1; o < SCAN_B; o <<= 1) {
        int a = (t >= o) ? sh[t - o] : 0;
        __syncthreads();
        sh[t] += a;
        __syncthreads();
    }
    if (i < N) {
        int excl = sh[t] - v + g_part[blockIdx.x];
        g_off[i] = excl;
        g_cur[i] = excl;
        g_norm[i] = rsqrtf(fmaxf((float)v, 1.0f));
    }
}

// ---------------- CSR fill: group src by dst ---------------------------------
__global__ void scatter_kernel(const int* __restrict__ src,
                               const int* __restrict__ dst, int E) {
    int e = blockIdx.x * blockDim.x + threadIdx.x;
    if (e < E) {
        int pos = atomicAdd(&g_cur[dst[e]], 1);
        g_csr[pos] = src[e];
    }
}

// ---------------- y0h = fp16((x @ W) * norm)  (100k x 256 @ 256 x 64) --------
__global__ void __launch_bounds__(256) gemm_kernel(const float* __restrict__ x,
                                                   const float* __restrict__ W,
                                                   int N) {
    __shared__ float Xs[64][65];
    __shared__ float Ws[64][64];

    const int t = threadIdx.x;
    const int rowbase = blockIdx.x * 64;
    const int tc = t & 15;
    const int tr = t >> 4;
    const int col0 = tc * 4;
    const int row0 = tr * 4;

    float acc[4][4] = {};

    for (int kc = 0; kc < IN_F; kc += 64) {
        #pragma unroll
        for (int i = 0; i < 16; i++) {
            int lin = t + i * 256;
            int r = lin >> 6;
            int c = lin & 63;
            int gr = rowbase + r;
            Xs[r][c] = (gr < N) ? x[(long long)gr * IN_F + kc + c] : 0.0f;
            Ws[r][c] = W[(kc + r) * OUT_F + c];
        }
        __syncthreads();

        #pragma unroll
        for (int k = 0; k < 64; k++) {
            float4 wv = *(const float4*)&Ws[k][col0];
            float xa0 = Xs[row0 + 0][k];
            float xa1 = Xs[row0 + 1][k];
            float xa2 = Xs[row0 + 2][k];
            float xa3 = Xs[row0 + 3][k];
            acc[0][0] += xa0 * wv.x; acc[0][1] += xa0 * wv.y;
            acc[0][2] += xa0 * wv.z; acc[0][3] += xa0 * wv.w;
            acc[1][0] += xa1 * wv.x; acc[1][1] += xa1 * wv.y;
            acc[1][2] += xa1 * wv.z; acc[1][3] += xa1 * wv.w;
            acc[2][0] += xa2 * wv.x; acc[2][1] += xa2 * wv.y;
            acc[2][2] += xa2 * wv.z; acc[2][3] += xa2 * wv.w;
            acc[3][0] += xa3 * wv.x; acc[3][1] += xa3 * wv.y;
            acc[3][2] += xa3 * wv.z; acc[3][3] += xa3 * wv.w;
        }
        __syncthreads();
    }

    #pragma unroll
    for (int r = 0; r < 4; r++) {
        int gr = rowbase + row0 + r;
        if (gr < N) {
            float nm = g_norm[gr];
            __half2 h0 = __floats2half2_rn(acc[r][0] * nm, acc[r][1] * nm);
            __half2 h1 = __floats2half2_rn(acc[r][2] * nm, acc[r][3] * nm);
            __half2* p = (__half2*)&g_y0h[(long long)gr * OUT_F + col0];
            p[0] = h0;
            p[1] = h1;
        }
    }
}

// ---------------- pull round 1: z1h[i] = fp16((sum y0h[s]) * norm[i]^2) ------
// one warp per node, each lane owns one half2 (2 features) of the 64-wide row
__global__ void __launch_bounds__(256) pull1_kernel(int N) {
    int warp = (blockIdx.x * blockDim.x + threadIdx.x) >> 5;
    if (warp >= N) return;
    int lane = threadIdx.x & 31;
    int base = g_off[warp];
    int deg = g_deg[warp];
    const __half2* yp = (const __half2*)g_y0h;
    const int* cp = g_csr + base;

    float ax = 0.0f, ay = 0.0f;
    int j = 0;
    for (; j + 4 <= deg; j += 4) {
        int s0 = __ldg(cp + j + 0);
        int s1 = __ldg(cp + j + 1);
        int s2 = __ldg(cp + j + 2);
        int s3 = __ldg(cp + j + 3);
        float2 v0 = __half22float2(__ldg(yp + s0 * 32 + lane));
        float2 v1 = __half22float2(__ldg(yp + s1 * 32 + lane));
        float2 v2 = __half22float2(__ldg(yp + s2 * 32 + lane));
        float2 v3 = __half22float2(__ldg(yp + s3 * 32 + lane));
        ax += v0.x + v1.x + v2.x + v3.x;
        ay += v0.y + v1.y + v2.y + v3.y;
    }
    for (; j < deg; j++) {
        int s = __ldg(cp + j);
        float2 v = __half22float2(__ldg(yp + s * 32 + lane));
        ax += v.x;
        ay += v.y;
    }
    float nm = g_norm[warp];
    nm *= nm;
    ((__half2*)g_z1h)[warp * 32 + lane] = __floats2half2_rn(ax * nm, ay * nm);
}

// ---------------- pull round 2: out[i] = (sum z1h[s]) * norm[i] + b ----------
__global__ void __launch_bounds__(256) pull2_kernel(const float* __restrict__ b,
                                                    float* __restrict__ out, int N) {
    int warp = (blockIdx.x * blockDim.x + threadIdx.x) >> 5;
    if (warp >= N) return;
    int lane = threadIdx.x & 31;
    int base = g_off[warp];
    int deg = g_deg[warp];
    const __half2* zp = (const __half2*)g_z1h;
    const int* cp = g_csr + base;

    float ax = 0.0f, ay = 0.0f;
    int j = 0;
    for (; j + 4 <= deg; j += 4) {
        int s0 = __ldg(cp + j + 0);
        int s1 = __ldg(cp + j + 1);
        int s2 = __ldg(cp + j + 2);
        int s3 = __ldg(cp + j + 3);
        float2 v0 = __half22float2(__ldg(zp + s0 * 32 + lane));
        float2 v1 = __half22float2(__ldg(zp + s1 * 32 + lane));
        float2 v2 = __half22float2(__ldg(zp + s2 * 32 + lane));
        float2 v3 = __half22float2(__ldg(zp + s3 * 32 + lane));
        ax += v0.x + v1.x + v2.x + v3.x;
        ay += v0.y + v1.y + v2.y + v3.y;
    }
    for (; j < deg; j++) {
        int s = __ldg(cp + j);
        float2 v = __half22float2(__ldg(zp + s * 32 + lane));
        ax += v.x;
        ay += v.y;
    }
    float nm = g_norm[warp];
    float2 bb = __ldg((const float2*)b + lane);
    ((float2*)out)[warp * 32 + lane] =
        make_float2(ax * nm + bb.x, ay * nm + bb.y);
}

// ---------------- launch -----------------------------------------------------
extern "C" void kernel_launch(void* const* d_in, const int* in_sizes, int n_in,
                              void* d_out, int out_size) {
    const float* x   = (const float*)d_in[0];
    const int*   src = (const int*)d_in[1];
    const int*   dst = (const int*)d_in[2];
    const float* W   = (const float*)d_in[3];
    const float* b   = (const float*)d_in[4];
    float*       out = (float*)d_out;

    const int N = in_sizes[0] / IN_F;   // 100000
    const int E = in_sizes[1];          // 3200000

    void* p_deg;
    cudaGetSymbolAddress(&p_deg, g_deg);
    cudaMemsetAsync(p_deg, 0, (size_t)N * sizeof(int));

    // CSR build
    deg_kernel<<<(E + 255) / 256, 256>>>(dst, E);
    scan1_kernel<<<SCAN_NB, SCAN_B>>>(N);
    scan2_kernel<<<1, 32>>>();
    scan3_kernel<<<SCAN_NB, SCAN_B>>>(N);
    scatter_kernel<<<(E + 255) / 256, 256>>>(src, dst, E);

    // projection (scaled by norm at write, fp16 out)
    gemm_kernel<<<(N + 63) / 64, 256>>>(x, W, N);

    // two pull rounds (warp per node)
    const int pb = 256;
    const int pgrid = (N * 32 + pb - 1) / pb;
    pull1_kernel<<<pgrid, pb>>>(N);
    pull2_kernel<<<pgrid, pb>>>(b, out, N);
}

// round 6
// speedup vs baseline: 1.9886x; 1.1068x over previous
#include <cuda_runtime.h>
#include <cuda_fp16.h>
#include <mma.h>

using namespace nvcuda;

// SGC K=2:  out = Prop(Prop(x @ W)) + b   (projection commuted to the front)
// - wmma fp16 tensor-core GEMM (fp32 accumulate)
// - pull aggregation over per-call CSR, rows padded to 4 for int4 index loads
// - features stored fp16 (half2/lane), fp32 accumulate

#define NN 100000
#define EE 3200000
#define IN_F 256
#define OUT_F 64
#define SCAN_B 1024
#define SCAN_NB ((NN + SCAN_B - 1) / SCAN_B)   // 98
#define CSR_CAP (EE + 3 * NN + 4)

// ---------------- scratch (static device globals; no allocation) -------------
__device__ __half g_y0h[NN * OUT_F];  // (x@W)*norm, fp16
__device__ __half g_z1h[NN * OUT_F];  // round-1 result * norm^2, fp16
__device__ float  g_norm[NN];
__device__ int    g_deg[NN];          // true degree
__device__ int    g_off[NN];          // padded CSR row offsets (mult of 4)
__device__ int    g_cur[NN];          // scatter cursors
__device__ int    g_csr[CSR_CAP];     // src ids grouped by dst (rows padded to 4)
__device__ int    g_part[SCAN_NB];    // scan partials

// ---------------- degree histogram -------------------------------------------
__global__ void deg_kernel(const int* __restrict__ dst, int E) {
    int e = blockIdx.x * blockDim.x + threadIdx.x;
    if (e < E) atomicAdd(&g_deg[dst[e]], 1);
}

// ---------------- scan stage 1: per-block sums of PADDED degrees -------------
__global__ void __launch_bounds__(SCAN_B) scan1_kernel(int N) {
    __shared__ int sh[SCAN_B];
    int t = threadIdx.x;
    int i = blockIdx.x * SCAN_B + t;
    int v = (i < N) ? ((g_deg[i] + 3) & ~3) : 0;
    sh[t] = v;
    __syncthreads();
    for (int o = SCAN_B / 2; o > 0; o >>= 1) {
        if (t < o) sh[t] += sh[t + o];
        __syncthreads();
    }
    if (t == 0) g_part[blockIdx.x] = sh[0];
}

// ---------------- scan stage 2: serial exclusive scan of partials ------------
__global__ void scan2_kernel() {
    if (threadIdx.x == 0) {
        int run = 0;
        for (int i = 0; i < SCAN_NB; i++) {
            int v = g_part[i];
            g_part[i] = run;
            run += v;
        }
    }
}

// ---------------- scan stage 3: padded exclusive scan + norm -----------------
__global__ void __launch_bounds__(SCAN_B) scan3_kernel(int N) {
    __shared__ int sh[SCAN_B];
    int t = threadIdx.x;
    int i = blockIdx.x * SCAN_B + t;
    int dv = (i < N) ? g_deg[i] : 0;
    int vp = (dv + 3) & ~3;
    sh[t] = vp;
    __syncthreads();
    for (int o = 1; o < SCAN_B; o <<= 1) {
        int a = (t >= o) ? sh[t - o] : 0;
        __syncthreads();
        sh[t] += a;
        __syncthreads();
    }
    if (i < N) {
        int excl = sh[t] - vp + g_part[blockIdx.x];
        g_off[i] = excl;
        g_cur[i] = excl;
        g_norm[i] = rsqrtf(fmaxf((float)dv, 1.0f));
    }
}

// ---------------- CSR fill: group src by dst ---------------------------------
__global__ void scatter_kernel(const int* __restrict__ src,
                               const int* __restrict__ dst, int E) {
    int e = blockIdx.x * blockDim.x + threadIdx.x;
    if (e < E) {
        int pos = atomicAdd(&g_cur[dst[e]], 1);
        g_csr[pos] = src[e];
    }
}

// ---------------- y0h = fp16((x @ W) * norm)  via wmma -----------------------
// block: 64 rows x 64 cols, 8 warps in 4x2 grid, each warp 16x32 (2 frags)
__global__ void __launch_bounds__(256) gemm_kernel(const float* __restrict__ x,
                                                   const float* __restrict__ W,
                                                   int N) {
    __shared__ __half As[64][72];    // x tile (fp16), padded ld
    __shared__ __half Bs[64][72];    // W chunk [k][n]
    __shared__ float  Os[64][68];    // fp32 result staging

    const int t = threadIdx.x;
    const int w = t >> 5;
    const int wr = w >> 1;           // 0..3 (row group)
    const int wc = w & 1;            // 0..1 (col group)
    const int rowbase = blockIdx.x * 64;

    wmma::fragment<wmma::accumulator, 16, 16, 16, float> acc0, acc1;
    wmma::fill_fragment(acc0, 0.0f);
    wmma::fill_fragment(acc1, 0.0f);

    for (int kc = 0; kc < IN_F; kc += 64) {
        #pragma unroll
        for (int i = 0; i < 16; i++) {
            int lin = t + i * 256;
            int r = lin >> 6;
            int c = lin & 63;
            int gr = rowbase + r;
            float xv = (gr < N) ? x[(long long)gr * IN_F + kc + c] : 0.0f;
            As[r][c] = __float2half(xv);
            Bs[r][c] = __float2half(W[(kc + r) * OUT_F + c]);
        }
        __syncthreads();

        #pragma unroll
        for (int ks = 0; ks < 4; ks++) {
            wmma::fragment<wmma::matrix_a, 16, 16, 16, __half, wmma::row_major> af;
            wmma::load_matrix_sync(af, &As[wr * 16][ks * 16], 72);
            wmma::fragment<wmma::matrix_b, 16, 16, 16, __half, wmma::row_major> bf0, bf1;
            wmma::load_matrix_sync(bf0, &Bs[ks * 16][wc * 32], 72);
            wmma::load_matrix_sync(bf1, &Bs[ks * 16][wc * 32 + 16], 72);
            wmma::mma_sync(acc0, af, bf0, acc0);
            wmma::mma_sync(acc1, af, bf1, acc1);
        }
        __syncthreads();
    }

    wmma::store_matrix_sync(&Os[wr * 16][wc * 32], acc0, 68, wmma::mem_row_major);
    wmma::store_matrix_sync(&Os[wr * 16][wc * 32 + 16], acc1, 68, wmma::mem_row_major);
    __syncthreads();

    // scale by norm, convert to fp16, write (4 threads/row, 16 cols each)
    int r = t >> 2;
    int c0 = (t & 3) * 16;
    int gr = rowbase + r;
    if (gr < N) {
        float nm = g_norm[gr];
        __half2* p = (__half2*)&g_y0h[(long long)gr * OUT_F + c0];
        #pragma unroll
        for (int k = 0; k < 8; k++) {
            p[k] = __floats2half2_rn(Os[r][c0 + 2 * k] * nm,
                                     Os[r][c0 + 2 * k + 1] * nm);
        }
    }
}

// ---------------- pull round 1: z1h[i] = fp16((sum y0h[s]) * norm[i]^2) ------
// one warp per node; int4 index loads (rows padded to 4)
__global__ void __launch_bounds__(256) pull1_kernel(int N) {
    int warp = (blockIdx.x * blockDim.x + threadIdx.x) >> 5;
    if (warp >= N) return;
    int lane = threadIdx.x & 31;
    int base = g_off[warp];
    int deg = g_deg[warp];
    const __half2* yp = (const __half2*)g_y0h;
    const int* cp = g_csr + base;

    float ax = 0.0f, ay = 0.0f;
    int j = 0;
    for (; j + 4 <= deg; j += 4) {
        int4 s = __ldg((const int4*)(cp + j));
        float2 v0 = __half22float2(__ldg(yp + s.x * 32 + lane));
        float2 v1 = __half22float2(__ldg(yp + s.y * 32 + lane));
        float2 v2 = __half22float2(__ldg(yp + s.z * 32 + lane));
        float2 v3 = __half22float2(__ldg(yp + s.w * 32 + lane));
        ax += v0.x + v1.x + v2.x + v3.x;
        ay += v0.y + v1.y + v2.y + v3.y;
    }
    if (j < deg) {
        int4 s = __ldg((const int4*)(cp + j));  // padded row: in-bounds
        {            float2 v = __half22float2(__ldg(yp + s.x * 32 + lane)); ax += v.x; ay += v.y; }
        if (j + 1 < deg) { float2 v = __half22float2(__ldg(yp + s.y * 32 + lane)); ax += v.x; ay += v.y; }
        if (j + 2 < deg) { float2 v = __half22float2(__ldg(yp + s.z * 32 + lane)); ax += v.x; ay += v.y; }
    }
    float nm = g_norm[warp];
    nm *= nm;
    ((__half2*)g_z1h)[warp * 32 + lane] = __floats2half2_rn(ax * nm, ay * nm);
}

// ---------------- pull round 2: out[i] = (sum z1h[s]) * norm[i] + b ----------
__global__ void __launch_bounds__(256) pull2_kernel(const float* __restrict__ b,
                                                    float* __restrict__ out, int N) {
    int warp = (blockIdx.x * blockDim.x + threadIdx.x) >> 5;
    if (warp >= N) return;
    int lane = threadIdx.x & 31;
    int base = g_off[warp];
    int deg = g_deg[warp];
    const __half2* zp = (const __half2*)g_z1h;
    const int* cp = g_csr + base;

    float ax = 0.0f, ay = 0.0f;
    int j = 0;
    for (; j + 4 <= deg; j += 4) {
        int4 s = __ldg((const int4*)(cp + j));
        float2 v0 = __half22float2(__ldg(zp + s.x * 32 + lane));
        float2 v1 = __half22float2(__ldg(zp + s.y * 32 + lane));
        float2 v2 = __half22float2(__ldg(zp + s.z * 32 + lane));
        float2 v3 = __half22float2(__ldg(zp + s.w * 32 + lane));
        ax += v0.x + v1.x + v2.x + v3.x;
        ay += v0.y + v1.y + v2.y + v3.y;
    }
    if (j < deg) {
        int4 s = __ldg((const int4*)(cp + j));
        {            float2 v = __half22float2(__ldg(zp + s.x * 32 + lane)); ax += v.x; ay += v.y; }
        if (j + 1 < deg) { float2 v = __half22float2(__ldg(zp + s.y * 32 + lane)); ax += v.x; ay += v.y; }
        if (j + 2 < deg) { float2 v = __half22float2(__ldg(zp + s.z * 32 + lane)); ax += v.x; ay += v.y; }
    }
    float nm = g_norm[warp];
    float2 bb = __ldg((const float2*)b + lane);
    ((float2*)out)[warp * 32 + lane] =
        make_float2(ax * nm + bb.x, ay * nm + bb.y);
}

// ---------------- launch -----------------------------------------------------
extern "C" void kernel_launch(void* const* d_in, const int* in_sizes, int n_in,
                              void* d_out, int out_size) {
    const float* x   = (const float*)d_in[0];
    const int*   src = (const int*)d_in[1];
    const int*   dst = (const int*)d_in[2];
    const float* W   = (const float*)d_in[3];
    const float* b   = (const float*)d_in[4];
    float*       out = (float*)d_out;

    const int N = in_sizes[0] / IN_F;   // 100000
    const int E = in_sizes[1];          // 3200000

    void* p_deg;
    cudaGetSymbolAddress(&p_deg, g_deg);
    cudaMemsetAsync(p_deg, 0, (size_t)N * sizeof(int));

    // CSR build (padded rows)
    deg_kernel<<<(E + 255) / 256, 256>>>(dst, E);
    scan1_kernel<<<SCAN_NB, SCAN_B>>>(N);
    scan2_kernel<<<1, 32>>>();
    scan3_kernel<<<SCAN_NB, SCAN_B>>>(N);
    scatter_kernel<<<(E + 255) / 256, 256>>>(src, dst, E);

    // tensor-core projection (scaled by norm at write, fp16 out)
    gemm_kernel<<<(N + 63) / 64, 256>>>(x, W, N);

    // two pull rounds (warp per node)
    const int pb = 256;
    const int pgrid = (N * 32 + pb - 1) / pb;
    pull1_kernel<<<pgrid, pb>>>(N);
    pull2_kernel<<<pgrid, pb>>>(b, out, N);
}